// round 15
// baseline (speedup 1.0000x reference)
#include <cuda_runtime.h>
#include <cuda_fp16.h>
#include <cstdint>

#define DK    4096
#define NCOL  64
#define TM    128
#define KC    32
#define NTILE 128
#define TOTCH (NTILE * 128)        // 16384 flat chunk-units
#define MAX_M 16384
#define N4    (MAX_M * NCOL / 4)   // 262144 float4
#define WSC   4096.0f
#define WSCI  (1.0f / 4096.0f)

// ---------------- device scratch ----------------
__device__ uint16_t     g_Whf[256 * 2 * 4 * 32 * 8];  // fp16 hi/lo B-fragments
__device__ float        g_Y[MAX_M * NCOL];
__device__ unsigned int g_absmax_bits;
__device__ unsigned int g_barcnt[2];

__constant__ float L_C[16] = {
    -1.0f, -0.6961928009986877f, -0.5250730514526367f, -0.39491748809814453f,
    -0.28444138169288635f, -0.18477343022823334f, -0.09105003625154495f, 0.0f,
    0.07958029955625534f, 0.16093020141124725f, 0.24611230194568634f,
    0.33791524171829224f, 0.44070982933044434f, 0.5626170039176941f,
    0.7229568362236023f, 1.0f };
__constant__ float MID_C[15] = {
    -0.8480964004993439f, -0.6106329262256622f, -0.4599952697753906f,
    -0.33967943489551544f, -0.23460740596055984f, -0.13791173323988914f,
    -0.045525018125772476f, 0.03979014977812767f, 0.1202552504837513f,
    0.2035212516784668f, 0.2920137718319893f, 0.3893125355243683f,
    0.5016634166240692f, 0.6427869200706482f, 0.8614784181118011f };

// ---------------- helpers ----------------
__device__ __forceinline__ void cp_async16(uint32_t dst, const void* src) {
    asm volatile("cp.async.cg.shared.global [%0], [%1], 16;" :: "r"(dst), "l"(src));
}
#define CP_COMMIT() asm volatile("cp.async.commit_group;")
#define CP_WAIT0()  asm volatile("cp.async.wait_group 0;")
#define CP_WAIT2()  asm volatile("cp.async.wait_group 2;")

__device__ __forceinline__ void lds128(uint4& v, uint32_t a) {
    asm volatile("ld.shared.v4.b32 {%0,%1,%2,%3}, [%4];"
                 : "=r"(v.x), "=r"(v.y), "=r"(v.z), "=r"(v.w) : "r"(a));
}
__device__ __forceinline__ float2 lds64f(uint32_t a) {
    float2 v;
    asm volatile("ld.shared.v2.f32 {%0,%1}, [%2];" : "=f"(v.x), "=f"(v.y) : "r"(a));
    return v;
}
__device__ __forceinline__ void red_addf(float* p, float v) {
    asm volatile("red.global.add.f32 [%0], %1;" :: "l"(p), "f"(v) : "memory");
}

__device__ __forceinline__ uint32_t f16x2_rn(float a, float b) {
    uint32_t r;
    asm("cvt.rn.f16x2.f32 %0, %1, %2;" : "=r"(r) : "f"(b), "f"(a));
    return r;
}
__device__ __forceinline__ void f16x2_unpack(uint32_t p, float& lo, float& hi) {
    asm("{.reg .f16 l, h; mov.b32 {l, h}, %2;"
        " cvt.f32.f16 %0, l; cvt.f32.f16 %1, h;}"
        : "=f"(lo), "=f"(hi) : "r"(p));
}
__device__ __forceinline__ void split_pair(float2 x, uint32_t& h, uint32_t& l) {
    h = f16x2_rn(x.x, x.y);
    float hx, hy;
    f16x2_unpack(h, hx, hy);
    l = f16x2_rn(x.x - hx, x.y - hy);
}

__device__ __forceinline__ void mma16(float4& d, uint32_t a0, uint32_t a1,
                                      uint32_t a2, uint32_t a3,
                                      uint32_t b0, uint32_t b1) {
    asm volatile(
        "mma.sync.aligned.m16n8k16.row.col.f32.f16.f16.f32 "
        "{%0,%1,%2,%3},{%4,%5,%6,%7},{%8,%9},{%0,%1,%2,%3};"
        : "+f"(d.x), "+f"(d.y), "+f"(d.z), "+f"(d.w)
        : "r"(a0), "r"(a1), "r"(a2), "r"(a3), "r"(b0), "r"(b1));
}

// grid-wide barrier: all CTAs co-resident (grid == nSM, occ 1); counters reset in k_w
__device__ __forceinline__ void grid_barrier(int which, unsigned int target) {
    __syncthreads();
    __threadfence();
    if (threadIdx.x == 0) {
        atomicAdd(&g_barcnt[which], 1u);
        while (((volatile unsigned int*)g_barcnt)[which] < target)
            __nanosleep(64);
    }
    __syncthreads();
}

__device__ __forceinline__ float nf4_bs(float v) {
    int idx = (v > MID_C[7]) ? 8 : 0;
    idx += (v > MID_C[idx + 3]) ? 4 : 0;
    idx += (v > MID_C[idx + 1]) ? 2 : 0;
    idx += (v > MID_C[idx]) ? 1 : 0;
    return L_C[idx];
}

// ---------------- kernel 1: W -> fp16 hi/lo fragments (coalesced stores) ----------
// grid 256 x block 128. Block = one k16 group (16 k-rows). Thread (grp=tid>>5, l):
// computes the 8 W values of fragment lane l in group grp:
//   n  = grp*16 + ntp*8 + (l>>2)
//   k  = k16*16 + reg*8 + (l&3)*2 + b      for (ntp, reg, b) in {0,1}^3
// then writes ONE uint4 for the hi fragment and ONE for lo (128B/warp, coalesced).
__global__ void k_w(const float* __restrict__ Bm, const float* __restrict__ A,
                    const float* __restrict__ ri) {
    __shared__ float sA[4096];
    __shared__ float sBm[1024];     // 16 rows x 64
    __shared__ float cs[64];
    __shared__ int cnt;
    int tid = threadIdx.x;
    int l = tid & 31, grp = tid >> 5;
    int k16 = blockIdx.x;

    // zero g_Y: 256 blocks x 128 threads x 8 float4 == 262144
#pragma unroll
    for (int i = 0; i < 8; i++)
        ((float4*)g_Y)[blockIdx.x * 1024 + i * 128 + tid] =
            make_float4(0.f, 0.f, 0.f, 0.f);
    if (blockIdx.x == 0 && tid == 0) {
        g_absmax_bits = 0u;
        g_barcnt[0] = 0u;
        g_barcnt[1] = 0u;
    }

    if (tid == 0) cnt = 0;
    __syncthreads();
    if (tid < 64) {
        float s = 1.0f / (1.0f + expf(-ri[tid]));
        int a = (s > 0.1f) ? 1 : 0;
        cs[tid] = (float)a;
        atomicAdd(&cnt, a);
    }

#pragma unroll
    for (int i = 0; i < 8; i++)
        ((float4*)sA)[i * 128 + tid] = ((const float4*)A)[i * 128 + tid];
#pragma unroll
    for (int i = 0; i < 2; i++)
        ((float4*)sBm)[i * 128 + tid] =
            ((const float4*)Bm)[(size_t)k16 * 256 + i * 128 + tid];
    __syncthreads();

    int nb = grp * 16 + (l >> 2);     // n for ntp=0 (+8 for ntp=1)
    int kb = (l & 3) * 2;             // local k for reg=0,b=0

    float acc[2][2][2];               // [ntp][reg][b]
#pragma unroll
    for (int i = 0; i < 2; i++)
#pragma unroll
        for (int j = 0; j < 2; j++)
#pragma unroll
            for (int b = 0; b < 2; b++) acc[i][j][b] = 0.0f;

#pragma unroll 4
    for (int r = 0; r < 64; r++) {
        float a0 = sA[r * 64 + nb];
        float a1 = sA[r * 64 + nb + 8];
        float b00 = sBm[(kb + 0) * 64 + r];
        float b01 = sBm[(kb + 1) * 64 + r];
        float b10 = sBm[(8 + kb + 0) * 64 + r];
        float b11 = sBm[(8 + kb + 1) * 64 + r];
        acc[0][0][0] = fmaf(b00, a0, acc[0][0][0]);
        acc[0][0][1] = fmaf(b01, a0, acc[0][0][1]);
        acc[0][1][0] = fmaf(b10, a0, acc[0][1][0]);
        acc[0][1][1] = fmaf(b11, a0, acc[0][1][1]);
        acc[1][0][0] = fmaf(b00, a1, acc[1][0][0]);
        acc[1][0][1] = fmaf(b01, a1, acc[1][0][1]);
        acc[1][1][0] = fmaf(b10, a1, acc[1][1][0]);
        acc[1][1][1] = fmaf(b11, a1, acc[1][1][1]);
    }

    int c_ = cnt;
    float cs0 = 0.25f * WSC * ((c_ > 0) ? cs[nb] : 1.0f);
    float cs1 = 0.25f * WSC * ((c_ > 0) ? cs[nb + 8] : 1.0f);

    uint16_t hu[8], lu[8];
#pragma unroll
    for (int ntp = 0; ntp < 2; ntp++)
#pragma unroll
        for (int reg = 0; reg < 2; reg++)
#pragma unroll
            for (int b = 0; b < 2; b++) {
                float w = acc[ntp][reg][b] * (ntp ? cs1 : cs0);
                __half hh = __float2half_rn(w);
                float  hf = __half2float(hh);
                __half hl = __float2half_rn(w - hf);
                int slot = (ntp * 2 + reg) * 2 + b;
                hu[slot] = __half_as_ushort(hh);
                lu[slot] = __half_as_ushort(hl);
            }

    uint4 hv, lv;
    hv.x = (uint32_t)hu[0] | ((uint32_t)hu[1] << 16);
    hv.y = (uint32_t)hu[2] | ((uint32_t)hu[3] << 16);
    hv.z = (uint32_t)hu[4] | ((uint32_t)hu[5] << 16);
    hv.w = (uint32_t)hu[6] | ((uint32_t)hu[7] << 16);
    lv.x = (uint32_t)lu[0] | ((uint32_t)lu[1] << 16);
    lv.y = (uint32_t)lu[2] | ((uint32_t)lu[3] << 16);
    lv.z = (uint32_t)lu[4] | ((uint32_t)lu[5] << 16);
    lv.w = (uint32_t)lu[6] | ((uint32_t)lu[7] << 16);

    uint4* frag = (uint4*)g_Whf;
    frag[((size_t)(k16 * 2 + 0) * 4 + grp) * 32 + l] = hv;
    frag[((size_t)(k16 * 2 + 1) * 4 + grp) * 32 + l] = lv;
}

// ---------------- kernel 2: fused GEMM (depth-3 pipeline) + absmax + quantize ----
#define SMA_SZ 18432                 // 128 rows * 144B
#define SMB_SZ 8192
#define SM_TOTAL (4 * SMA_SZ + 4 * SMB_SZ)   // 106496

__global__ void __launch_bounds__(128, 1) k_gemm(const float* __restrict__ x,
                                                 float* __restrict__ out,
                                                 const float* __restrict__ qs) {
    extern __shared__ char smem[];
    uint32_t sbA = (uint32_t)__cvta_generic_to_shared(smem);
    uint32_t sbB = sbA + 4 * SMA_SZ;

    int tid = threadIdx.x;
    int wid = tid >> 5, l = tid & 31;
    int mh = wid >> 1, nh = wid & 1;
    int r_in = l >> 2, cq = l & 3;
    const char* wsrc = (const char*)g_Whf;
    unsigned int nblk = gridDim.x;

    // ---- phase 1: GEMM over this CTA's flat chunk range ----
    int g0 = (int)(((long long)blockIdx.x * TOTCH) / nblk);
    int g1 = (int)(((long long)(blockIdx.x + 1) * TOTCH) / nblk);

    int g = g0;
    while (g < g1) {
        int tile = g >> 7;
        int c0 = g & 127;
        int rem = g1 - g;
        int segn = (128 - c0 < rem) ? (128 - c0) : rem;
        int cend = c0 + segn;
        const float* xblk = x + (size_t)tile * TM * DK;

        float4 C[4][4], S[4][4];
#pragma unroll
        for (int a = 0; a < 4; a++)
#pragma unroll
            for (int b = 0; b < 4; b++) {
                C[a][b] = make_float4(0.f, 0.f, 0.f, 0.f);
                S[a][b] = make_float4(0.f, 0.f, 0.f, 0.f);
            }

        CP_WAIT0();        // drain previous segment's groups
        __syncthreads();   // previous segment's buffers free before reuse

        // prologue: issue 3 groups (c0, c0+1, c0+2), empty-commit padding
#pragma unroll
        for (int p = 0; p < 3; p++) {
            int cc = c0 + p;
            if (cc < cend) {
                uint32_t aoff = sbA + (uint32_t)((cc & 3) * SMA_SZ);
                uint32_t boff = sbB + (uint32_t)((cc & 3) * SMB_SZ);
                int k0 = cc * KC;
                const char* bs = wsrc + (size_t)cc * SMB_SZ;
#pragma unroll
                for (int i = 0; i < 8; i++) {
                    int idx = i * 128 + tid;
                    int row = idx >> 3, q = idx & 7;
                    cp_async16(aoff + (uint32_t)(row * 144 + q * 16),
                               xblk + (size_t)row * DK + k0 + q * 4);
                }
#pragma unroll
                for (int i = 0; i < 4; i++) {
                    int idx = i * 128 + tid;
                    cp_async16(boff + (uint32_t)(idx * 16), bs + (size_t)idx * 16);
                }
            }
            CP_COMMIT();
        }

#pragma unroll 1
        for (int c = c0; c < cend; c++) {
            CP_WAIT2();        // group c complete (3 in flight max)
            __syncthreads();

            {
                int cc = c + 3;
                if (cc < cend) {
                    uint32_t aoff = sbA + (uint32_t)((cc & 3) * SMA_SZ);
                    uint32_t boff = sbB + (uint32_t)((cc & 3) * SMB_SZ);
                    int k0 = cc * KC;
                    const char* bs = wsrc + (size_t)cc * SMB_SZ;
#pragma unroll
                    for (int i = 0; i < 8; i++) {
                        int idx = i * 128 + tid;
                        int row = idx >> 3, q = idx & 7;
                        cp_async16(aoff + (uint32_t)(row * 144 + q * 16),
                                   xblk + (size_t)row * DK + k0 + q * 4);
                    }
#pragma unroll
                    for (int i = 0; i < 4; i++) {
                        int idx = i * 128 + tid;
                        cp_async16(boff + (uint32_t)(idx * 16), bs + (size_t)idx * 16);
                    }
                }
                CP_COMMIT();   // always commit: keeps pending == 3 invariant
            }

            uint32_t ab = sbA + (uint32_t)((c & 3) * SMA_SZ);
            uint32_t bb = sbB + (uint32_t)((c & 3) * SMB_SZ);

#pragma unroll
            for (int ks = 0; ks < 2; ks++) {
                uint4 BH[2], BL[2];
#pragma unroll
                for (int gg = 0; gg < 2; gg++) {
                    uint32_t bh  = bb + (uint32_t)((((ks * 2 + 0) * 4 + nh * 2 + gg) * 32 + l) * 16);
                    uint32_t blo = bb + (uint32_t)((((ks * 2 + 1) * 4 + nh * 2 + gg) * 32 + l) * 16);
                    lds128(BH[gg], bh);
                    lds128(BL[gg], blo);
                }
#pragma unroll
                for (int rt = 0; rt < 4; rt++) {
                    int row = mh * 64 + rt * 16 + r_in;
                    uint32_t ra = ab + (uint32_t)(row * 144 + (ks * 16 + cq * 2) * 4);
                    float2 p0 = lds64f(ra);
                    float2 p1 = lds64f(ra + 8 * 144);
                    float2 p2 = lds64f(ra + 32);
                    float2 p3 = lds64f(ra + 8 * 144 + 32);

                    uint32_t ah0, al0, ah1, al1, ah2, al2, ah3, al3;
                    split_pair(p0, ah0, al0);
                    split_pair(p1, ah1, al1);
                    split_pair(p2, ah2, al2);
                    split_pair(p3, ah3, al3);

                    mma16(C[rt][0], ah0, ah1, ah2, ah3, BH[0].x, BH[0].y);
                    mma16(C[rt][1], ah0, ah1, ah2, ah3, BH[0].z, BH[0].w);
                    mma16(C[rt][2], ah0, ah1, ah2, ah3, BH[1].x, BH[1].y);
                    mma16(C[rt][3], ah0, ah1, ah2, ah3, BH[1].z, BH[1].w);

                    mma16(C[rt][0], ah0, ah1, ah2, ah3, BL[0].x, BL[0].y);
                    mma16(C[rt][1], ah0, ah1, ah2, ah3, BL[0].z, BL[0].w);
                    mma16(C[rt][2], ah0, ah1, ah2, ah3, BL[1].x, BL[1].y);
                    mma16(C[rt][3], ah0, ah1, ah2, ah3, BL[1].z, BL[1].w);

                    mma16(C[rt][0], al0, al1, al2, al3, BH[0].x, BH[0].y);
                    mma16(C[rt][1], al0, al1, al2, al3, BH[0].z, BH[0].w);
                    mma16(C[rt][2], al0, al1, al2, al3, BH[1].x, BH[1].y);
                    mma16(C[rt][3], al0, al1, al2, al3, BH[1].z, BH[1].w);
                }
            }

            if ((c & 15) == 15 || c + 1 == cend) {
#pragma unroll
                for (int a = 0; a < 4; a++)
#pragma unroll
                    for (int b = 0; b < 4; b++) {
                        S[a][b].x += C[a][b].x; S[a][b].y += C[a][b].y;
                        S[a][b].z += C[a][b].z; S[a][b].w += C[a][b].w;
                        C[a][b] = make_float4(0.f, 0.f, 0.f, 0.f);
                    }
            }
        }

#pragma unroll
        for (int rt = 0; rt < 4; rt++)
#pragma unroll
            for (int nt = 0; nt < 4; nt++) {
                float4 v = S[rt][nt];
                int row = tile * TM + mh * 64 + rt * 16 + r_in;
                int col = nh * 32 + nt * 8 + cq * 2;
                red_addf(&g_Y[(size_t)row * NCOL + col],           v.x * WSCI);
                red_addf(&g_Y[(size_t)row * NCOL + col + 1],       v.y * WSCI);
                red_addf(&g_Y[(size_t)(row + 8) * NCOL + col],     v.z * WSCI);
                red_addf(&g_Y[(size_t)(row + 8) * NCOL + col + 1], v.w * WSCI);
            }

        g += segn;
    }

    // ---- barrier 1: all partial sums landed ----
    grid_barrier(0, nblk);

    // ---- phase 2: abs-max over this CTA's slice; cache slice in smem ----
    unsigned int per = (N4 + nblk - 1) / nblk;   // 1725 float4 = 27600 B <= smem
    unsigned int base = blockIdx.x * per;
    unsigned int end = base + per;
    if (end > N4) end = N4;
    float4* ycache = (float4*)smem;

    float mx = 0.0f;
    {
        unsigned int j = 0;
        for (unsigned int i = base + tid; i < end; i += 128, j++) {
            float4 y = ((const float4*)g_Y)[i];
            ycache[j * 128 + tid] = y;
            mx = fmaxf(mx, fmaxf(fmaxf(fabsf(y.x), fabsf(y.y)),
                                 fmaxf(fabsf(y.z), fabsf(y.w))));
        }
    }
#pragma unroll
    for (int off = 16; off; off >>= 1)
        mx = fmaxf(mx, __shfl_xor_sync(0xffffffffu, mx, off));
    if (l == 0) atomicMax(&g_absmax_bits, __float_as_uint(mx));

    // ---- barrier 2: absmax final ----
    grid_barrier(1, nblk);

    // ---- phase 3: NF4 quantize from the smem cache ----
    float absmax = __uint_as_float(*((volatile unsigned int*)&g_absmax_bits));
    float qscale = qs[0];
    if (absmax > 0.0f) {
        float inv = 1.0f / absmax;
        float osc = absmax * qscale;
        unsigned int j = 0;
        for (unsigned int i = base + tid; i < end; i += 128, j++) {
            float4 y = ycache[j * 128 + tid];
            float4 o;
            o.x = nf4_bs(y.x * inv) * osc;
            o.y = nf4_bs(y.y * inv) * osc;
            o.z = nf4_bs(y.z * inv) * osc;
            o.w = nf4_bs(y.w * inv) * osc;
            ((float4*)out)[i] = o;
        }
    } else {
        unsigned int j = 0;
        for (unsigned int i = base + tid; i < end; i += 128, j++) {
            float4 y = ycache[j * 128 + tid];
            y.x *= qscale; y.y *= qscale; y.z *= qscale; y.w *= qscale;
            ((float4*)out)[i] = y;
        }
    }
}

// ---------------- launch ----------------
extern "C" void kernel_launch(void* const* d_in, const int* in_sizes, int n_in,
                              void* d_out, int out_size) {
    const float* x  = (const float*)d_in[0];   // [4,4096,4096]
    const float* A  = (const float*)d_in[1];   // [64,64]
    const float* Bm = (const float*)d_in[2];   // [4096,64]
    const float* qs = (const float*)d_in[3];   // [1]
    const float* ri = (const float*)d_in[4];   // [64]
    float* out = (float*)d_out;

    int dev = 0, nsm = 148;
    cudaGetDevice(&dev);
    cudaDeviceGetAttribute(&nsm, cudaDevAttrMultiProcessorCount, dev);

    cudaFuncSetAttribute(k_gemm, cudaFuncAttributeMaxDynamicSharedMemorySize, SM_TOTAL);

    k_w<<<256, 128>>>(Bm, A, ri);
    k_gemm<<<nsm, 128, SM_TOTAL>>>(x, out, qs);
}

// round 16
// speedup vs baseline: 1.0172x; 1.0172x over previous
#include <cuda_runtime.h>
#include <cuda_fp16.h>
#include <cstdint>

#define DK    4096
#define NCOL  64
#define TM    128
#define KC    32
#define NTILE 128
#define TOTCH (NTILE * 128)        // 16384 flat chunk-units
#define MAX_M 16384
#define N4    (MAX_M * NCOL / 4)   // 262144 float4
#define WSC   4096.0f
#define WSCI  (1.0f / 4096.0f)

// ---------------- device scratch ----------------
__device__ uint16_t     g_Whf[256 * 2 * 4 * 32 * 8];  // fp16 hi/lo B-fragments
__device__ float        g_Y[MAX_M * NCOL];
__device__ unsigned int g_absmax_bits;
__device__ unsigned int g_barcnt[2];

__constant__ float L_C[16] = {
    -1.0f, -0.6961928009986877f, -0.5250730514526367f, -0.39491748809814453f,
    -0.28444138169288635f, -0.18477343022823334f, -0.09105003625154495f, 0.0f,
    0.07958029955625534f, 0.16093020141124725f, 0.24611230194568634f,
    0.33791524171829224f, 0.44070982933044434f, 0.5626170039176941f,
    0.7229568362236023f, 1.0f };
__constant__ float MID_C[15] = {
    -0.8480964004993439f, -0.6106329262256622f, -0.4599952697753906f,
    -0.33967943489551544f, -0.23460740596055984f, -0.13791173323988914f,
    -0.045525018125772476f, 0.03979014977812767f, 0.1202552504837513f,
    0.2035212516784668f, 0.2920137718319893f, 0.3893125355243683f,
    0.5016634166240692f, 0.6427869200706482f, 0.8614784181118011f };

// ---------------- helpers ----------------
__device__ __forceinline__ void cp_async16(uint32_t dst, const void* src) {
    asm volatile("cp.async.cg.shared.global [%0], [%1], 16;" :: "r"(dst), "l"(src));
}
#define CP_COMMIT() asm volatile("cp.async.commit_group;")
#define CP_WAIT0()  asm volatile("cp.async.wait_group 0;")
#define CP_WAIT3()  asm volatile("cp.async.wait_group 3;")

__device__ __forceinline__ void lds128(uint4& v, uint32_t a) {
    asm volatile("ld.shared.v4.b32 {%0,%1,%2,%3}, [%4];"
                 : "=r"(v.x), "=r"(v.y), "=r"(v.z), "=r"(v.w) : "r"(a));
}
__device__ __forceinline__ float2 lds64f(uint32_t a) {
    float2 v;
    asm volatile("ld.shared.v2.f32 {%0,%1}, [%2];" : "=f"(v.x), "=f"(v.y) : "r"(a));
    return v;
}
__device__ __forceinline__ void red_addf(float* p, float v) {
    asm volatile("red.global.add.f32 [%0], %1;" :: "l"(p), "f"(v) : "memory");
}

__device__ __forceinline__ uint32_t f16x2_rn(float a, float b) {
    uint32_t r;
    asm("cvt.rn.f16x2.f32 %0, %1, %2;" : "=r"(r) : "f"(b), "f"(a));
    return r;
}
__device__ __forceinline__ void f16x2_unpack(uint32_t p, float& lo, float& hi) {
    asm("{.reg .f16 l, h; mov.b32 {l, h}, %2;"
        " cvt.f32.f16 %0, l; cvt.f32.f16 %1, h;}"
        : "=f"(lo), "=f"(hi) : "r"(p));
}
__device__ __forceinline__ void split_pair(float2 x, uint32_t& h, uint32_t& l) {
    h = f16x2_rn(x.x, x.y);
    float hx, hy;
    f16x2_unpack(h, hx, hy);
    l = f16x2_rn(x.x - hx, x.y - hy);
}

__device__ __forceinline__ void mma16(float4& d, uint32_t a0, uint32_t a1,
                                      uint32_t a2, uint32_t a3,
                                      uint32_t b0, uint32_t b1) {
    asm volatile(
        "mma.sync.aligned.m16n8k16.row.col.f32.f16.f16.f32 "
        "{%0,%1,%2,%3},{%4,%5,%6,%7},{%8,%9},{%0,%1,%2,%3};"
        : "+f"(d.x), "+f"(d.y), "+f"(d.z), "+f"(d.w)
        : "r"(a0), "r"(a1), "r"(a2), "r"(a3), "r"(b0), "r"(b1));
}

// grid-wide barrier: all CTAs co-resident (grid == nSM, occ 1); counters reset in k_w
__device__ __forceinline__ void grid_barrier(int which, unsigned int target) {
    __syncthreads();
    __threadfence();
    if (threadIdx.x == 0) {
        atomicAdd(&g_barcnt[which], 1u);
        while (((volatile unsigned int*)g_barcnt)[which] < target)
            __nanosleep(64);
    }
    __syncthreads();
}

__device__ __forceinline__ float nf4_bs(float v) {
    int idx = (v > MID_C[7]) ? 8 : 0;
    idx += (v > MID_C[idx + 3]) ? 4 : 0;
    idx += (v > MID_C[idx + 1]) ? 2 : 0;
    idx += (v > MID_C[idx]) ? 1 : 0;
    return L_C[idx];
}

// ---------------- kernel 1: W -> fp16 hi/lo fragments; zero Y; reset counters ----
// grid 256 x block 256: block b computes k-rows [16b, 16b+16)  (R13 best-measured)
__global__ void k_w(const float* __restrict__ Bm, const float* __restrict__ A,
                    const float* __restrict__ ri) {
    __shared__ float sA[4096];
    __shared__ float sBm[1024];
    __shared__ float cs[64];
    __shared__ int cnt;
    int tid = threadIdx.x;

    // zero g_Y: 256 blocks x 256 threads x 4 float4 == 262144
#pragma unroll
    for (int i = 0; i < 4; i++)
        ((float4*)g_Y)[blockIdx.x * 1024 + i * 256 + tid] =
            make_float4(0.f, 0.f, 0.f, 0.f);
    if (blockIdx.x == 0 && tid == 0) {
        g_absmax_bits = 0u;
        g_barcnt[0] = 0u;
        g_barcnt[1] = 0u;
    }

    if (tid == 0) cnt = 0;
    __syncthreads();
    if (tid < 64) {
        float s = 1.0f / (1.0f + expf(-ri[tid]));
        int a = (s > 0.1f) ? 1 : 0;
        cs[tid] = (float)a;
        atomicAdd(&cnt, a);
    }

#pragma unroll
    for (int i = 0; i < 4; i++)
        ((float4*)sA)[i * 256 + tid] = ((const float4*)A)[i * 256 + tid];
    ((float4*)sBm)[tid] = ((const float4*)Bm)[blockIdx.x * 256 + tid];
    __syncthreads();

    int c_ = cnt;
#pragma unroll
    for (int i = 0; i < 4; i++) {
        int idx = i * 256 + tid;
        int kk = idx >> 6, n = idx & 63;
        float acc = 0.0f;
#pragma unroll 8
        for (int r = 0; r < 64; r++)
            acc = fmaf(sBm[kk * 64 + r], sA[r * 64 + n], acc);
        float colscale = 0.25f * WSC * ((c_ > 0) ? cs[n] : 1.0f);
        float w = acc * colscale;

        __half hh = __float2half_rn(w);
        float  hf = __half2float(hh);
        __half hl = __float2half_rn(w - hf);

        int k = blockIdx.x * 16 + kk;
        int k16 = k >> 4, kr = k & 15;
        int reg = kr >> 3;
        int l   = ((n & 7) << 2) | ((kr & 7) >> 1);
        int grp = n >> 4;
        int ntp = (n >> 3) & 1;
        size_t base = ((((size_t)(k16 * 2 + 0) * 4 + grp) * 32 + l) * 8)
                      + (size_t)(ntp * 2 + reg) * 2 + (kr & 1);
        g_Whf[base]                      = __half_as_ushort(hh);
        g_Whf[base + (size_t)4 * 32 * 8] = __half_as_ushort(hl);
    }
}

// ---------------- kernel 2: fused GEMM (depth-4 pipeline) + absmax + quantize ----
#define SMA_SZ 18432                 // 128 rows * 144B
#define SMB_SZ 8192
#define NBUF   8
#define SM_TOTAL (NBUF * SMA_SZ + NBUF * SMB_SZ)   // 212992

__global__ void __launch_bounds__(128, 1) k_gemm(const float* __restrict__ x,
                                                 float* __restrict__ out,
                                                 const float* __restrict__ qs) {
    extern __shared__ char smem[];
    uint32_t sbA = (uint32_t)__cvta_generic_to_shared(smem);
    uint32_t sbB = sbA + NBUF * SMA_SZ;

    int tid = threadIdx.x;
    int wid = tid >> 5, l = tid & 31;
    int mh = wid >> 1, nh = wid & 1;
    int r_in = l >> 2, cq = l & 3;
    const char* wsrc = (const char*)g_Whf;
    unsigned int nblk = gridDim.x;

    // ---- phase 1: GEMM over this CTA's flat chunk range ----
    int g0 = (int)(((long long)blockIdx.x * TOTCH) / nblk);
    int g1 = (int)(((long long)(blockIdx.x + 1) * TOTCH) / nblk);

    int g = g0;
    while (g < g1) {
        int tile = g >> 7;
        int c0 = g & 127;
        int rem = g1 - g;
        int segn = (128 - c0 < rem) ? (128 - c0) : rem;
        int cend = c0 + segn;
        const float* xblk = x + (size_t)tile * TM * DK;

        float4 C[4][4], S[4][4];
#pragma unroll
        for (int a = 0; a < 4; a++)
#pragma unroll
            for (int b = 0; b < 4; b++) {
                C[a][b] = make_float4(0.f, 0.f, 0.f, 0.f);
                S[a][b] = make_float4(0.f, 0.f, 0.f, 0.f);
            }

        CP_WAIT0();        // drain previous segment's groups
        __syncthreads();   // previous segment's buffers free before reuse

        // prologue: issue 4 groups (c0..c0+3), empty-commit padding
#pragma unroll
        for (int p = 0; p < 4; p++) {
            int cc = c0 + p;
            if (cc < cend) {
                uint32_t aoff = sbA + (uint32_t)((cc & (NBUF - 1)) * SMA_SZ);
                uint32_t boff = sbB + (uint32_t)((cc & (NBUF - 1)) * SMB_SZ);
                int k0 = cc * KC;
                const char* bs = wsrc + (size_t)cc * SMB_SZ;
#pragma unroll
                for (int i = 0; i < 8; i++) {
                    int idx = i * 128 + tid;
                    int row = idx >> 3, q = idx & 7;
                    cp_async16(aoff + (uint32_t)(row * 144 + q * 16),
                               xblk + (size_t)row * DK + k0 + q * 4);
                }
#pragma unroll
                for (int i = 0; i < 4; i++) {
                    int idx = i * 128 + tid;
                    cp_async16(boff + (uint32_t)(idx * 16), bs + (size_t)idx * 16);
                }
            }
            CP_COMMIT();
        }

#pragma unroll 1
        for (int c = c0; c < cend; c++) {
            CP_WAIT3();        // group c complete (4 in flight max)
            __syncthreads();

            {
                int cc = c + 4;
                if (cc < cend) {
                    uint32_t aoff = sbA + (uint32_t)((cc & (NBUF - 1)) * SMA_SZ);
                    uint32_t boff = sbB + (uint32_t)((cc & (NBUF - 1)) * SMB_SZ);
                    int k0 = cc * KC;
                    const char* bs = wsrc + (size_t)cc * SMB_SZ;
#pragma unroll
                    for (int i = 0; i < 8; i++) {
                        int idx = i * 128 + tid;
                        int row = idx >> 3, q = idx & 7;
                        cp_async16(aoff + (uint32_t)(row * 144 + q * 16),
                                   xblk + (size_t)row * DK + k0 + q * 4);
                    }
#pragma unroll
                    for (int i = 0; i < 4; i++) {
                        int idx = i * 128 + tid;
                        cp_async16(boff + (uint32_t)(idx * 16), bs + (size_t)idx * 16);
                    }
                }
                CP_COMMIT();   // always commit: keeps pending == 4 invariant
            }

            uint32_t ab = sbA + (uint32_t)((c & (NBUF - 1)) * SMA_SZ);
            uint32_t bb = sbB + (uint32_t)((c & (NBUF - 1)) * SMB_SZ);

#pragma unroll
            for (int ks = 0; ks < 2; ks++) {
                uint4 BH[2], BL[2];
#pragma unroll
                for (int gg = 0; gg < 2; gg++) {
                    uint32_t bh  = bb + (uint32_t)((((ks * 2 + 0) * 4 + nh * 2 + gg) * 32 + l) * 16);
                    uint32_t blo = bb + (uint32_t)((((ks * 2 + 1) * 4 + nh * 2 + gg) * 32 + l) * 16);
                    lds128(BH[gg], bh);
                    lds128(BL[gg], blo);
                }
#pragma unroll
                for (int rt = 0; rt < 4; rt++) {
                    int row = mh * 64 + rt * 16 + r_in;
                    uint32_t ra = ab + (uint32_t)(row * 144 + (ks * 16 + cq * 2) * 4);
                    float2 p0 = lds64f(ra);
                    float2 p1 = lds64f(ra + 8 * 144);
                    float2 p2 = lds64f(ra + 32);
                    float2 p3 = lds64f(ra + 8 * 144 + 32);

                    uint32_t ah0, al0, ah1, al1, ah2, al2, ah3, al3;
                    split_pair(p0, ah0, al0);
                    split_pair(p1, ah1, al1);
                    split_pair(p2, ah2, al2);
                    split_pair(p3, ah3, al3);

                    mma16(C[rt][0], ah0, ah1, ah2, ah3, BH[0].x, BH[0].y);
                    mma16(C[rt][1], ah0, ah1, ah2, ah3, BH[0].z, BH[0].w);
                    mma16(C[rt][2], ah0, ah1, ah2, ah3, BH[1].x, BH[1].y);
                    mma16(C[rt][3], ah0, ah1, ah2, ah3, BH[1].z, BH[1].w);

                    mma16(C[rt][0], ah0, ah1, ah2, ah3, BL[0].x, BL[0].y);
                    mma16(C[rt][1], ah0, ah1, ah2, ah3, BL[0].z, BL[0].w);
                    mma16(C[rt][2], ah0, ah1, ah2, ah3, BL[1].x, BL[1].y);
                    mma16(C[rt][3], ah0, ah1, ah2, ah3, BL[1].z, BL[1].w);

                    mma16(C[rt][0], al0, al1, al2, al3, BH[0].x, BH[0].y);
                    mma16(C[rt][1], al0, al1, al2, al3, BH[0].z, BH[0].w);
                    mma16(C[rt][2], al0, al1, al2, al3, BH[1].x, BH[1].y);
                    mma16(C[rt][3], al0, al1, al2, al3, BH[1].z, BH[1].w);
                }
            }

            if ((c & 15) == 15 || c + 1 == cend) {
#pragma unroll
                for (int a = 0; a < 4; a++)
#pragma unroll
                    for (int b = 0; b < 4; b++) {
                        S[a][b].x += C[a][b].x; S[a][b].y += C[a][b].y;
                        S[a][b].z += C[a][b].z; S[a][b].w += C[a][b].w;
                        C[a][b] = make_float4(0.f, 0.f, 0.f, 0.f);
                    }
            }
        }

#pragma unroll
        for (int rt = 0; rt < 4; rt++)
#pragma unroll
            for (int nt = 0; nt < 4; nt++) {
                float4 v = S[rt][nt];
                int row = tile * TM + mh * 64 + rt * 16 + r_in;
                int col = nh * 32 + nt * 8 + cq * 2;
                red_addf(&g_Y[(size_t)row * NCOL + col],           v.x * WSCI);
                red_addf(&g_Y[(size_t)row * NCOL + col + 1],       v.y * WSCI);
                red_addf(&g_Y[(size_t)(row + 8) * NCOL + col],     v.z * WSCI);
                red_addf(&g_Y[(size_t)(row + 8) * NCOL + col + 1], v.w * WSCI);
            }

        g += segn;
    }

    // ---- barrier 1: all partial sums landed ----
    grid_barrier(0, nblk);

    // ---- phase 2: abs-max over this CTA's slice; cache slice in smem ----
    unsigned int per = (N4 + nblk - 1) / nblk;   // 1725 float4 = 27600 B <= smem
    unsigned int base = blockIdx.x * per;
    unsigned int end = base + per;
    if (end > N4) end = N4;
    float4* ycache = (float4*)smem;

    float mx = 0.0f;
    {
        unsigned int j = 0;
        for (unsigned int i = base + tid; i < end; i += 128, j++) {
            float4 y = ((const float4*)g_Y)[i];
            ycache[j * 128 + tid] = y;
            mx = fmaxf(mx, fmaxf(fmaxf(fabsf(y.x), fabsf(y.y)),
                                 fmaxf(fabsf(y.z), fabsf(y.w))));
        }
    }
#pragma unroll
    for (int off = 16; off; off >>= 1)
        mx = fmaxf(mx, __shfl_xor_sync(0xffffffffu, mx, off));
    if (l == 0) atomicMax(&g_absmax_bits, __float_as_uint(mx));

    // ---- barrier 2: absmax final ----
    grid_barrier(1, nblk);

    // ---- phase 3: NF4 quantize from the smem cache ----
    float absmax = __uint_as_float(*((volatile unsigned int*)&g_absmax_bits));
    float qscale = qs[0];
    if (absmax > 0.0f) {
        float inv = 1.0f / absmax;
        float osc = absmax * qscale;
        unsigned int j = 0;
        for (unsigned int i = base + tid; i < end; i += 128, j++) {
            float4 y = ycache[j * 128 + tid];
            float4 o;
            o.x = nf4_bs(y.x * inv) * osc;
            o.y = nf4_bs(y.y * inv) * osc;
            o.z = nf4_bs(y.z * inv) * osc;
            o.w = nf4_bs(y.w * inv) * osc;
            ((float4*)out)[i] = o;
        }
    } else {
        unsigned int j = 0;
        for (unsigned int i = base + tid; i < end; i += 128, j++) {
            float4 y = ycache[j * 128 + tid];
            y.x *= qscale; y.y *= qscale; y.z *= qscale; y.w *= qscale;
            ((float4*)out)[i] = y;
        }
    }
}

// ---------------- launch ----------------
extern "C" void kernel_launch(void* const* d_in, const int* in_sizes, int n_in,
                              void* d_out, int out_size) {
    const float* x  = (const float*)d_in[0];   // [4,4096,4096]
    const float* A  = (const float*)d_in[1];   // [64,64]
    const float* Bm = (const float*)d_in[2];   // [4096,64]
    const float* qs = (const float*)d_in[3];   // [1]
    const float* ri = (const float*)d_in[4];   // [64]
    float* out = (float*)d_out;

    int dev = 0, nsm = 148;
    cudaGetDevice(&dev);
    cudaDeviceGetAttribute(&nsm, cudaDevAttrMultiProcessorCount, dev);

    cudaFuncSetAttribute(k_gemm, cudaFuncAttributeMaxDynamicSharedMemorySize, SM_TOTAL);

    k_w<<<256, 256>>>(Bm, A, ri);
    k_gemm<<<nsm, 128, SM_TOTAL>>>(x, out, qs);
}

// round 17
// speedup vs baseline: 1.0300x; 1.0127x over previous
#include <cuda_runtime.h>
#include <cuda_fp16.h>
#include <cstdint>

#define DK    4096
#define NCOL  64
#define TM    128
#define KC    32
#define NTILE 128
#define TOTCH (NTILE * 128)        // 16384 flat chunk-units
#define MAX_M 16384
#define N4    (MAX_M * NCOL / 4)   // 262144 float4
#define WSC   4096.0f
#define WSCI  (1.0f / 4096.0f)

// ---------------- device scratch ----------------
__device__ uint16_t     g_Whf[256 * 2 * 4 * 32 * 8];  // fp16 hi/lo B-fragments
__device__ float        g_Y[MAX_M * NCOL];
__device__ unsigned int g_absmax_bits;
__device__ unsigned int g_barcnt[2];

__constant__ float L_C[16] = {
    -1.0f, -0.6961928009986877f, -0.5250730514526367f, -0.39491748809814453f,
    -0.28444138169288635f, -0.18477343022823334f, -0.09105003625154495f, 0.0f,
    0.07958029955625534f, 0.16093020141124725f, 0.24611230194568634f,
    0.33791524171829224f, 0.44070982933044434f, 0.5626170039176941f,
    0.7229568362236023f, 1.0f };
__constant__ float MID_C[15] = {
    -0.8480964004993439f, -0.6106329262256622f, -0.4599952697753906f,
    -0.33967943489551544f, -0.23460740596055984f, -0.13791173323988914f,
    -0.045525018125772476f, 0.03979014977812767f, 0.1202552504837513f,
    0.2035212516784668f, 0.2920137718319893f, 0.3893125355243683f,
    0.5016634166240692f, 0.6427869200706482f, 0.8614784181118011f };

// ---------------- helpers ----------------
__device__ __forceinline__ void cp_async16(uint32_t dst, const void* src) {
    asm volatile("cp.async.cg.shared.global [%0], [%1], 16;" :: "r"(dst), "l"(src));
}
#define CP_COMMIT() asm volatile("cp.async.commit_group;")
#define CP_WAIT0()  asm volatile("cp.async.wait_group 0;")
#define CP_WAIT3()  asm volatile("cp.async.wait_group 3;")

__device__ __forceinline__ void lds128(uint4& v, uint32_t a) {
    asm volatile("ld.shared.v4.b32 {%0,%1,%2,%3}, [%4];"
                 : "=r"(v.x), "=r"(v.y), "=r"(v.z), "=r"(v.w) : "r"(a));
}
__device__ __forceinline__ float2 lds64f(uint32_t a) {
    float2 v;
    asm volatile("ld.shared.v2.f32 {%0,%1}, [%2];" : "=f"(v.x), "=f"(v.y) : "r"(a));
    return v;
}
__device__ __forceinline__ void red_addf(float* p, float v) {
    asm volatile("red.global.add.f32 [%0], %1;" :: "l"(p), "f"(v) : "memory");
}

__device__ __forceinline__ uint32_t f16x2_rn(float a, float b) {
    uint32_t r;
    asm("cvt.rn.f16x2.f32 %0, %1, %2;" : "=r"(r) : "f"(b), "f"(a));
    return r;
}
__device__ __forceinline__ void f16x2_unpack(uint32_t p, float& lo, float& hi) {
    asm("{.reg .f16 l, h; mov.b32 {l, h}, %2;"
        " cvt.f32.f16 %0, l; cvt.f32.f16 %1, h;}"
        : "=f"(lo), "=f"(hi) : "r"(p));
}
__device__ __forceinline__ void split_pair(float2 x, uint32_t& h, uint32_t& l) {
    h = f16x2_rn(x.x, x.y);
    float hx, hy;
    f16x2_unpack(h, hx, hy);
    l = f16x2_rn(x.x - hx, x.y - hy);
}

__device__ __forceinline__ void mma16(float4& d, uint32_t a0, uint32_t a1,
                                      uint32_t a2, uint32_t a3,
                                      uint32_t b0, uint32_t b1) {
    asm volatile(
        "mma.sync.aligned.m16n8k16.row.col.f32.f16.f16.f32 "
        "{%0,%1,%2,%3},{%4,%5,%6,%7},{%8,%9},{%0,%1,%2,%3};"
        : "+f"(d.x), "+f"(d.y), "+f"(d.z), "+f"(d.w)
        : "r"(a0), "r"(a1), "r"(a2), "r"(a3), "r"(b0), "r"(b1));
}

// grid-wide barrier: all CTAs co-resident (grid == nSM, occ 1); counters reset in k_w
__device__ __forceinline__ void grid_barrier(int which, unsigned int target) {
    __syncthreads();
    __threadfence();
    if (threadIdx.x == 0) {
        atomicAdd(&g_barcnt[which], 1u);
        while (((volatile unsigned int*)g_barcnt)[which] < target)
            __nanosleep(64);
    }
    __syncthreads();
}

__device__ __forceinline__ float nf4_bs(float v) {
    int idx = (v > MID_C[7]) ? 8 : 0;
    idx += (v > MID_C[idx + 3]) ? 4 : 0;
    idx += (v > MID_C[idx + 1]) ? 2 : 0;
    idx += (v > MID_C[idx]) ? 1 : 0;
    return L_C[idx];
}

// ---------------- kernel 1: W -> fp16 hi/lo fragments; zero Y; reset counters ----
// grid 256 x block 256: block b computes k-rows [16b, 16b+16)
__global__ void k_w(const float* __restrict__ Bm, const float* __restrict__ A,
                    const float* __restrict__ ri) {
    __shared__ float sA[4096];
    __shared__ float sBm[1024];
    __shared__ float cs[64];
    __shared__ int cnt;
    int tid = threadIdx.x;

    // zero g_Y: 256 blocks x 256 threads x 4 float4 == 262144
#pragma unroll
    for (int i = 0; i < 4; i++)
        ((float4*)g_Y)[blockIdx.x * 1024 + i * 256 + tid] =
            make_float4(0.f, 0.f, 0.f, 0.f);
    if (blockIdx.x == 0 && tid == 0) {
        g_absmax_bits = 0u;
        g_barcnt[0] = 0u;
        g_barcnt[1] = 0u;
    }

    if (tid == 0) cnt = 0;
    __syncthreads();
    if (tid < 64) {
        float s = 1.0f / (1.0f + expf(-ri[tid]));
        int a = (s > 0.1f) ? 1 : 0;
        cs[tid] = (float)a;
        atomicAdd(&cnt, a);
    }

#pragma unroll
    for (int i = 0; i < 4; i++)
        ((float4*)sA)[i * 256 + tid] = ((const float4*)A)[i * 256 + tid];
    ((float4*)sBm)[tid] = ((const float4*)Bm)[blockIdx.x * 256 + tid];
    __syncthreads();

    int c_ = cnt;
#pragma unroll
    for (int i = 0; i < 4; i++) {
        int idx = i * 256 + tid;
        int kk = idx >> 6, n = idx & 63;
        float acc = 0.0f;
#pragma unroll 8
        for (int r = 0; r < 64; r++)
            acc = fmaf(sBm[kk * 64 + r], sA[r * 64 + n], acc);
        float colscale = 0.25f * WSC * ((c_ > 0) ? cs[n] : 1.0f);
        float w = acc * colscale;

        __half hh = __float2half_rn(w);
        float  hf = __half2float(hh);
        __half hl = __float2half_rn(w - hf);

        int k = blockIdx.x * 16 + kk;
        int k16 = k >> 4, kr = k & 15;
        int reg = kr >> 3;
        int l   = ((n & 7) << 2) | ((kr & 7) >> 1);
        int grp = n >> 4;
        int ntp = (n >> 3) & 1;
        size_t base = ((((size_t)(k16 * 2 + 0) * 4 + grp) * 32 + l) * 8)
                      + (size_t)(ntp * 2 + reg) * 2 + (kr & 1);
        g_Whf[base]                      = __half_as_ushort(hh);
        g_Whf[base + (size_t)4 * 32 * 8] = __half_as_ushort(hl);
    }
}

// ---------------- kernel 2: seamless-pipeline GEMM + absmax + quantize ----------
#define SMA_SZ 18432                 // 128 rows * 144B
#define SMB_SZ 8192
#define NBUF   8
#define SM_TOTAL (NBUF * SMA_SZ + NBUF * SMB_SZ)   // 212992

__global__ void __launch_bounds__(128, 1) k_gemm(const float* __restrict__ x,
                                                 float* __restrict__ out,
                                                 const float* __restrict__ qs) {
    extern __shared__ char smem[];
    uint32_t sbA = (uint32_t)__cvta_generic_to_shared(smem);
    uint32_t sbB = sbA + NBUF * SMA_SZ;

    int tid = threadIdx.x;
    int wid = tid >> 5, l = tid & 31;
    int mh = wid >> 1, nh = wid & 1;
    int r_in = l >> 2, cq = l & 3;
    const char* wsrc = (const char*)g_Whf;
    unsigned int nblk = gridDim.x;

    // prefetch address decomposition (loop-invariant)
    int arow = tid >> 3;            // + i*16 : A row
    int aq   = (tid & 7) * 4;       // float offset within k-slice

    // ---- phase 1: GEMM over this CTA's flat chunk range (seamless pipeline) ----
    int g0 = (int)(((long long)blockIdx.x * TOTCH) / nblk);
    int g1 = (int)(((long long)(blockIdx.x + 1) * TOTCH) / nblk);

    float4 C[4][4], S[4][4];
#pragma unroll
    for (int a = 0; a < 4; a++)
#pragma unroll
        for (int b = 0; b < 4; b++) {
            C[a][b] = make_float4(0.f, 0.f, 0.f, 0.f);
            S[a][b] = make_float4(0.f, 0.f, 0.f, 0.f);
        }

    // prologue: issue 4 groups (g0..g0+3)
#pragma unroll
    for (int p = 0; p < 4; p++) {
        int cc = g0 + p;
        if (cc < g1) {
            uint32_t aoff = sbA + (uint32_t)((cc & (NBUF - 1)) * SMA_SZ);
            uint32_t boff = sbB + (uint32_t)((cc & (NBUF - 1)) * SMB_SZ);
            const float* xsrc = x + (size_t)(cc >> 7) * TM * DK + (cc & 127) * KC;
            const char* bs = wsrc + (size_t)(cc & 127) * SMB_SZ;
#pragma unroll
            for (int i = 0; i < 8; i++) {
                int row = arow + i * 16;
                cp_async16(aoff + (uint32_t)(row * 144 + aq * 4),
                           xsrc + (size_t)row * DK + aq);
            }
#pragma unroll
            for (int i = 0; i < 4; i++) {
                int idx = i * 128 + tid;
                cp_async16(boff + (uint32_t)(idx * 16), bs + (size_t)idx * 16);
            }
        }
        CP_COMMIT();
    }

#pragma unroll 1
    for (int gi = g0; gi < g1; gi++) {
        CP_WAIT3();        // group gi complete (4 in flight max)
        __syncthreads();

        {
            int cc = gi + 4;
            if (cc < g1) {
                uint32_t aoff = sbA + (uint32_t)((cc & (NBUF - 1)) * SMA_SZ);
                uint32_t boff = sbB + (uint32_t)((cc & (NBUF - 1)) * SMB_SZ);
                const float* xsrc = x + (size_t)(cc >> 7) * TM * DK + (cc & 127) * KC;
                const char* bs = wsrc + (size_t)(cc & 127) * SMB_SZ;
#pragma unroll
                for (int i = 0; i < 8; i++) {
                    int row = arow + i * 16;
                    cp_async16(aoff + (uint32_t)(row * 144 + aq * 4),
                               xsrc + (size_t)row * DK + aq);
                }
#pragma unroll
                for (int i = 0; i < 4; i++) {
                    int idx = i * 128 + tid;
                    cp_async16(boff + (uint32_t)(idx * 16), bs + (size_t)idx * 16);
                }
            }
            CP_COMMIT();   // always commit: keeps pending == 4 invariant
        }

        uint32_t ab = sbA + (uint32_t)((gi & (NBUF - 1)) * SMA_SZ);
        uint32_t bb = sbB + (uint32_t)((gi & (NBUF - 1)) * SMB_SZ);

#pragma unroll
        for (int ks = 0; ks < 2; ks++) {
            uint4 BH[2], BL[2];
#pragma unroll
            for (int gg = 0; gg < 2; gg++) {
                uint32_t bh  = bb + (uint32_t)((((ks * 2 + 0) * 4 + nh * 2 + gg) * 32 + l) * 16);
                uint32_t blo = bb + (uint32_t)((((ks * 2 + 1) * 4 + nh * 2 + gg) * 32 + l) * 16);
                lds128(BH[gg], bh);
                lds128(BL[gg], blo);
            }
#pragma unroll
            for (int rt = 0; rt < 4; rt++) {
                int row = mh * 64 + rt * 16 + r_in;
                uint32_t ra = ab + (uint32_t)(row * 144 + (ks * 16 + cq * 2) * 4);
                float2 p0 = lds64f(ra);
                float2 p1 = lds64f(ra + 8 * 144);
                float2 p2 = lds64f(ra + 32);
                float2 p3 = lds64f(ra + 8 * 144 + 32);

                uint32_t ah0, al0, ah1, al1, ah2, al2, ah3, al3;
                split_pair(p0, ah0, al0);
                split_pair(p1, ah1, al1);
                split_pair(p2, ah2, al2);
                split_pair(p3, ah3, al3);

                mma16(C[rt][0], ah0, ah1, ah2, ah3, BH[0].x, BH[0].y);
                mma16(C[rt][1], ah0, ah1, ah2, ah3, BH[0].z, BH[0].w);
                mma16(C[rt][2], ah0, ah1, ah2, ah3, BH[1].x, BH[1].y);
                mma16(C[rt][3], ah0, ah1, ah2, ah3, BH[1].z, BH[1].w);

                mma16(C[rt][0], ah0, ah1, ah2, ah3, BL[0].x, BL[0].y);
                mma16(C[rt][1], ah0, ah1, ah2, ah3, BL[0].z, BL[0].w);
                mma16(C[rt][2], ah0, ah1, ah2, ah3, BL[1].x, BL[1].y);
                mma16(C[rt][3], ah0, ah1, ah2, ah3, BL[1].z, BL[1].w);

                mma16(C[rt][0], al0, al1, al2, al3, BH[0].x, BH[0].y);
                mma16(C[rt][1], al0, al1, al2, al3, BH[0].z, BH[0].w);
                mma16(C[rt][2], al0, al1, al2, al3, BH[1].x, BH[1].y);
                mma16(C[rt][3], al0, al1, al2, al3, BH[1].z, BH[1].w);
            }
        }

        bool tile_end = ((gi & 127) == 127) || (gi == g1 - 1);
        if (((gi & 15) == 15) || tile_end) {
#pragma unroll
            for (int a = 0; a < 4; a++)
#pragma unroll
                for (int b = 0; b < 4; b++) {
                    S[a][b].x += C[a][b].x; S[a][b].y += C[a][b].y;
                    S[a][b].z += C[a][b].z; S[a][b].w += C[a][b].w;
                    C[a][b] = make_float4(0.f, 0.f, 0.f, 0.f);
                }
        }

        if (tile_end) {
            int tile = gi >> 7;
#pragma unroll
            for (int rt = 0; rt < 4; rt++)
#pragma unroll
                for (int nt = 0; nt < 4; nt++) {
                    float4 v = S[rt][nt];
                    int row = tile * TM + mh * 64 + rt * 16 + r_in;
                    int col = nh * 32 + nt * 8 + cq * 2;
                    red_addf(&g_Y[(size_t)row * NCOL + col],           v.x * WSCI);
                    red_addf(&g_Y[(size_t)row * NCOL + col + 1],       v.y * WSCI);
                    red_addf(&g_Y[(size_t)(row + 8) * NCOL + col],     v.z * WSCI);
                    red_addf(&g_Y[(size_t)(row + 8) * NCOL + col + 1], v.w * WSCI);
                    S[rt][nt] = make_float4(0.f, 0.f, 0.f, 0.f);
                }
        }
    }

    // drain remaining (empty) groups before smem reuse as ycache
    CP_WAIT0();

    // ---- barrier 1: all partial sums landed ----
    grid_barrier(0, nblk);

    // ---- phase 2: abs-max over this CTA's slice; cache slice in smem ----
    unsigned int per = (N4 + nblk - 1) / nblk;   // 1725 float4 = 27600 B <= smem
    unsigned int base = blockIdx.x * per;
    unsigned int end = base + per;
    if (end > N4) end = N4;
    float4* ycache = (float4*)smem;

    float mx = 0.0f;
    {
        unsigned int j = 0;
        for (unsigned int i = base + tid; i < end; i += 128, j++) {
            float4 y = ((const float4*)g_Y)[i];
            ycache[j * 128 + tid] = y;
            mx = fmaxf(mx, fmaxf(fmaxf(fabsf(y.x), fabsf(y.y)),
                                 fmaxf(fabsf(y.z), fabsf(y.w))));
        }
    }
#pragma unroll
    for (int off = 16; off; off >>= 1)
        mx = fmaxf(mx, __shfl_xor_sync(0xffffffffu, mx, off));
    if (l == 0) atomicMax(&g_absmax_bits, __float_as_uint(mx));

    // ---- barrier 2: absmax final ----
    grid_barrier(1, nblk);

    // ---- phase 3: NF4 quantize from the smem cache ----
    float absmax = __uint_as_float(*((volatile unsigned int*)&g_absmax_bits));
    float qscale = qs[0];
    if (absmax > 0.0f) {
        float inv = 1.0f / absmax;
        float osc = absmax * qscale;
        unsigned int j = 0;
        for (unsigned int i = base + tid; i < end; i += 128, j++) {
            float4 y = ycache[j * 128 + tid];
            float4 o;
            o.x = nf4_bs(y.x * inv) * osc;
            o.y = nf4_bs(y.y * inv) * osc;
            o.z = nf4_bs(y.z * inv) * osc;
            o.w = nf4_bs(y.w * inv) * osc;
            ((float4*)out)[i] = o;
        }
    } else {
        unsigned int j = 0;
        for (unsigned int i = base + tid; i < end; i += 128, j++) {
            float4 y = ycache[j * 128 + tid];
            y.x *= qscale; y.y *= qscale; y.z *= qscale; y.w *= qscale;
            ((float4*)out)[i] = y;
        }
    }
}

// ---------------- launch ----------------
extern "C" void kernel_launch(void* const* d_in, const int* in_sizes, int n_in,
                              void* d_out, int out_size) {
    const float* x  = (const float*)d_in[0];   // [4,4096,4096]
    const float* A  = (const float*)d_in[1];   // [64,64]
    const float* Bm = (const float*)d_in[2];   // [4096,64]
    const float* qs = (const float*)d_in[3];   // [1]
    const float* ri = (const float*)d_in[4];   // [64]
    float* out = (float*)d_out;

    int dev = 0, nsm = 148;
    cudaGetDevice(&dev);
    cudaDeviceGetAttribute(&nsm, cudaDevAttrMultiProcessorCount, dev);

    cudaFuncSetAttribute(k_gemm, cudaFuncAttributeMaxDynamicSharedMemorySize, SM_TOTAL);

    k_w<<<256, 256>>>(Bm, A, ri);
    k_gemm<<<nsm, 128, SM_TOTAL>>>(x, out, qs);
}